// round 3
// baseline (speedup 1.0000x reference)
// EDESC_18296560681209 — fused (z@D) per-cluster sum-of-squares + row-normalize + z passthrough.
// sm_103 BASE target (toolchain emits .target sm_103 — no tcgen05!). wmma HMMA GEMM,
// cp.async 3-stage pipeline, epilogue reduces zD tile to per-cluster partial sums.
#include <cuda_runtime.h>
#include <cuda_fp16.h>
#include <mma.h>
#include <cstdint>
#include <cstddef>

using namespace nvcuda;

#define NROWS 16384
#define NZ    8192
#define NCLU  16

// GEMM tiling
#define BM 128
#define BN 128
#define BK 64
#define NK (NZ / BK)          // 128 k-chunks
#define STAGES 3
#define LDT 80                 // smem row stride in halves (64 + 16 pad; 160B, 32B-aligned frags)
#define TILE_BYTES (128 * LDT * 2)          // 20480 per operand tile
#define STAGE_BYTES (2 * TILE_BYTES)        // 40960 (A + B)
#define GEMM_SMEM (STAGES * STAGE_BYTES)    // 122880  (>= epilogue C buf 128*132*4 = 67584)

// ---------------- device scratch (static; allocation-free rule) ----------------
__device__ __align__(256) __half g_zh[(size_t)NROWS * NZ];   // z fp16 row-major [16384][8192]
__device__ __align__(256) __half g_Dt[(size_t)NZ * NZ];      // D^T fp16 row-major [n][k]
__device__ float g_part[(size_t)NROWS * 64];                  // per (row, n-tile) partial sums

// ---------------- helpers ----------------
__device__ __forceinline__ uint32_t smem_u32(const void* p) {
    uint32_t a;
    asm("{ .reg .u64 t; cvta.to.shared.u64 t, %1; cvt.u32.u64 %0, t; }" : "=r"(a) : "l"(p));
    return a;
}
__device__ __forceinline__ void cpasync16(uint32_t dst, const void* src) {
    asm volatile("cp.async.cg.shared.global [%0], [%1], 16;" :: "r"(dst), "l"(src));
}
#define CP_COMMIT()  asm volatile("cp.async.commit_group;" ::: "memory")
#define CP_WAIT1()   asm volatile("cp.async.wait_group 1;" ::: "memory")

// ---------------- kernel 1: z -> fp16 + fp32 passthrough ----------------
__global__ __launch_bounds__(256) void conv_z(const float* __restrict__ z, float* __restrict__ outz) {
    const size_t t = (size_t)blockIdx.x * 256 + threadIdx.x;   // 16,777,216 threads, 8 floats each
    const size_t base = t * 8;
    const float4* src = reinterpret_cast<const float4*>(z + base);
    float4 v0 = src[0], v1 = src[1];
    float4* dst = reinterpret_cast<float4*>(outz + base);
    dst[0] = v0; dst[1] = v1;
    __half2 h[4];
    h[0] = __floats2half2_rn(v0.x, v0.y);
    h[1] = __floats2half2_rn(v0.z, v0.w);
    h[2] = __floats2half2_rn(v1.x, v1.y);
    h[3] = __floats2half2_rn(v1.z, v1.w);
    *reinterpret_cast<uint4*>(g_zh + base) = *reinterpret_cast<uint4*>(h);
}

// ---------------- kernel 2: D -> fp16 transposed ----------------
__global__ __launch_bounds__(256) void conv_D(const float* __restrict__ Dm) {
    __shared__ __half t[64][65];
    const int kb = blockIdx.x * 64, nb = blockIdx.y * 64;
    const int c = threadIdx.x & 63, rq = threadIdx.x >> 6;   // 4 rows per iter
#pragma unroll
    for (int i = 0; i < 16; ++i) {
        int r = i * 4 + rq;
        t[r][c] = __float2half_rn(Dm[(size_t)(kb + r) * NZ + nb + c]);
    }
    __syncthreads();
#pragma unroll
    for (int i = 0; i < 16; ++i) {
        int r = i * 4 + rq;
        g_Dt[(size_t)(nb + r) * NZ + kb + c] = t[c][r];
    }
}

// ---------------- kernel 3: fused GEMM + per-tile sum-of-squares ----------------
__global__ __launch_bounds__(256) void gemm_k() {
    extern __shared__ unsigned char smem[];
    const uint32_t smem_b = smem_u32(smem);

    // grid swizzle: 8192 CTAs = 128 m-tiles x 64 n-tiles, n grouped by 16 for L2 reuse
    const int g = blockIdx.x;
    const int ng = g >> 11;            // 0..3
    const int rem = g & 2047;
    const int m = rem >> 4;            // 0..127
    const int n = ng * 16 + (rem & 15);   // 0..63

    const int tid = threadIdx.x;
    const int wid = tid >> 5;
    const int wm = wid & 1;            // warp m index (2)
    const int wn = wid >> 1;           // warp n index (4)

    const __half* gA = g_zh + (size_t)m * 128 * NZ;   // + kc*64
    const __half* gB = g_Dt + (size_t)n * 128 * NZ;

    // per-thread load slots: 1024 16B chunks per operand tile, 4 per thread
    const int c0 = tid;                 // chunk ids c0 + i*256
    // acc
    wmma::fragment<wmma::accumulator, 16, 16, 16, float> acc[4][2];
#pragma unroll
    for (int i = 0; i < 4; ++i)
#pragma unroll
        for (int j = 0; j < 2; ++j) wmma::fill_fragment(acc[i][j], 0.0f);

    auto issue_load = [&](int kc, int st) {
        const uint32_t sA = smem_b + st * STAGE_BYTES;
        const uint32_t sB = sA + TILE_BYTES;
        const __half* pa = gA + kc * 64;
        const __half* pb = gB + kc * 64;
#pragma unroll
        for (int i = 0; i < 4; ++i) {
            int c = c0 + i * 256;
            int row = c >> 3, seg = c & 7;
            cpasync16(sA + row * (LDT * 2) + seg * 16, pa + (size_t)row * NZ + seg * 8);
            cpasync16(sB + row * (LDT * 2) + seg * 16, pb + (size_t)row * NZ + seg * 8);
        }
    };

    // prologue: stages 0,1
    issue_load(0, 0); CP_COMMIT();
    issue_load(1, 1); CP_COMMIT();

#pragma unroll 1
    for (int kc = 0; kc < NK; ++kc) {
        CP_WAIT1();                 // chunk kc resident
        __syncthreads();            // all warps past previous compute; loads visible
        if (kc + 2 < NK) issue_load(kc + 2, (kc + 2) % STAGES);
        CP_COMMIT();

        const int st = kc % STAGES;
        const __half* Ab = reinterpret_cast<const __half*>(smem + st * STAGE_BYTES);
        const __half* Bb = reinterpret_cast<const __half*>(smem + st * STAGE_BYTES + TILE_BYTES);
#pragma unroll
        for (int ks = 0; ks < 4; ++ks) {
            wmma::fragment<wmma::matrix_a, 16, 16, 16, __half, wmma::row_major> a[4];
            wmma::fragment<wmma::matrix_b, 16, 16, 16, __half, wmma::col_major> b[2];
#pragma unroll
            for (int i = 0; i < 4; ++i)
                wmma::load_matrix_sync(a[i], Ab + (wm * 64 + i * 16) * LDT + ks * 16, LDT);
#pragma unroll
            for (int j = 0; j < 2; ++j)
                wmma::load_matrix_sync(b[j], Bb + (wn * 32 + j * 16) * LDT + ks * 16, LDT);
#pragma unroll
            for (int i = 0; i < 4; ++i)
#pragma unroll
                for (int j = 0; j < 2; ++j)
                    wmma::mma_sync(acc[i][j], a[i], b[j], acc[i][j]);
        }
    }

    // ---- epilogue: spill C tile to smem, reduce sum-of-squares per row ----
    __syncthreads();
    float* C = reinterpret_cast<float*>(smem);    // [128][132]
#pragma unroll
    for (int i = 0; i < 4; ++i)
#pragma unroll
        for (int j = 0; j < 2; ++j)
            wmma::store_matrix_sync(C + (wm * 64 + i * 16) * 132 + (wn * 32 + j * 16),
                                    acc[i][j], 132, wmma::mem_row_major);
    __syncthreads();

    if (tid < 128) {
        const float4* p = reinterpret_cast<const float4*>(C + tid * 132);
        float s = 0.0f;
#pragma unroll
        for (int q = 0; q < 32; ++q) {
            float4 v = p[q];
            s = fmaf(v.x, v.x, s); s = fmaf(v.y, v.y, s);
            s = fmaf(v.z, v.z, s); s = fmaf(v.w, v.w, s);
        }
        g_part[(size_t)(m * 128 + tid) * 64 + n] = s;   // deterministic, no atomics
    }
}

// ---------------- kernel 4: finalize s = (s + eta*d) / rowsum ----------------
__global__ __launch_bounds__(256) void fin_k(float* __restrict__ outs) {
    const int row = blockIdx.x * 256 + threadIdx.x;   // 0..16383
    const float4* p = reinterpret_cast<const float4*>(g_part + (size_t)row * 64);
    float s[16];
    float sum = 0.0f;
#pragma unroll
    for (int c = 0; c < 16; ++c) {
        float4 v = p[c];                               // 4 n-tiles = one cluster
        s[c] = v.x + v.y + v.z + v.w + 2560.0f;        // + ETA * D_SUB
        sum += s[c];
    }
    const float inv = 1.0f / sum;                      // (eta+1)*d cancels
    float4* op = reinterpret_cast<float4*>(outs + (size_t)row * NCLU);
#pragma unroll
    for (int q = 0; q < 4; ++q)
        op[q] = make_float4(s[4 * q] * inv, s[4 * q + 1] * inv, s[4 * q + 2] * inv, s[4 * q + 3] * inv);
}

// ---------------- launch ----------------
extern "C" void kernel_launch(void* const* d_in, const int* in_sizes, int n_in,
                              void* d_out, int out_size) {
    const float* z  = (const float*)d_in[0];
    const float* Dm = (const float*)d_in[1];
    float* out = (float*)d_out;                        // [0,262144): s ; then z fp32

    cudaFuncSetAttribute(gemm_k, cudaFuncAttributeMaxDynamicSharedMemorySize, GEMM_SMEM);

    conv_z<<<65536, 256>>>(z, out + (size_t)NROWS * NCLU);
    conv_D<<<dim3(128, 128), 256>>>(Dm);
    gemm_k<<<8192, 256, GEMM_SMEM>>>();
    fin_k<<<NROWS / 256, 256>>>(out);
}